// round 5
// baseline (speedup 1.0000x reference)
#include <cuda_runtime.h>

// DiceFromLabelsLoss — single fused kernel, round 5.
// Per (batch, class c in 1..9): P=#(yp==c), T=#(yt==c), I=#(yp==c && yt==c).
// loss = 1 - sum_n sum_c [P+T>0] * (T / sumT / NB) * (2I/(P+T))
//
// Hot loop: guard-free exact-trip windows of 9 grid-stride iterations,
// loads front-batched 6 at a time (3 int4 pairs) for MLP, packed 64-bit
// histogram accumulators (10 classes x 6-bit fields, <=36 increments per
// window), flushed into 16-bit-packed per-class counters (15 regs).

#define NB 4
#define NC 9

__device__ unsigned g_hist[NB][3][NC];  // [batch][{P,T,I}][class-1]
__device__ unsigned g_done;

__device__ __forceinline__ void proc(const int4 a, const int4 b,
                                     unsigned long long& aP,
                                     unsigned long long& aT,
                                     unsigned long long& aI) {
    const int va[4] = {a.x, a.y, a.z, a.w};
    const int vb[4] = {b.x, b.y, b.z, b.w};
#pragma unroll
    for (int j = 0; j < 4; j++) {
        const unsigned long long pa = 1ull << (6 * va[j]);
        aP += pa;
        aT += 1ull << (6 * vb[j]);
        if (va[j] == vb[j]) aI += pa;
    }
}

__device__ __forceinline__ void flush(const unsigned long long aP,
                                      const unsigned long long aT,
                                      const unsigned long long aI,
                                      unsigned* pkP, unsigned* pkT, unsigned* pkI) {
#pragma unroll
    for (int c = 1; c <= NC; c++) {
        const int r = (c - 1) >> 1;
        const int sh = ((c - 1) & 1) * 16;
        pkP[r] += (((unsigned)(aP >> (6 * c))) & 63u) << sh;
        pkT[r] += (((unsigned)(aT >> (6 * c))) & 63u) << sh;
        pkI[r] += (((unsigned)(aI >> (6 * c))) & 63u) << sh;
    }
}

__global__ __launch_bounds__(512, 2) void dice_fused_kernel(
    const int4* __restrict__ yp, const int4* __restrict__ yt,
    int n4_per_batch, int nblocks_total, float* __restrict__ out) {
    const int n = blockIdx.y;
    const int4* __restrict__ p = yp + (size_t)n * n4_per_batch;
    const int4* __restrict__ t = yt + (size_t)n * n4_per_batch;
    const int stride = blockDim.x * gridDim.x;

    // 16-bit packed per-class counters: class c -> pk[(c-1)>>1], half (c-1)&1.
    // Per-thread per-class max ~= 4*(nfull+1) ~= 112 << 65535: no overflow.
    unsigned pkP[5], pkT[5], pkI[5];
#pragma unroll
    for (int r = 0; r < 5; r++) { pkP[r] = 0u; pkT[r] = 0u; pkI[r] = 0u; }

    __shared__ unsigned sh[3 * NC];
    __shared__ unsigned s_last;
    if (threadIdx.x < 3 * NC) sh[threadIdx.x] = 0u;
    __syncthreads();

    int i = blockIdx.x * blockDim.x + threadIdx.x;
    const int nfull = n4_per_batch / stride;  // guard-free iterations per thread

    int k = 0;
    while (k + 9 <= nfull) {
        unsigned long long aP = 0ull, aT = 0ull, aI = 0ull;
#pragma unroll
        for (int g = 0; g < 3; g++) {
            // Front-batch 6 LDG.128 before any consumption (MLP).
            const int4 A0 = p[i];
            const int4 B0 = t[i];
            const int4 A1 = p[i + stride];
            const int4 B1 = t[i + stride];
            const int4 A2 = p[i + 2 * stride];
            const int4 B2 = t[i + 2 * stride];
            i += 3 * stride;
            proc(A0, B0, aP, aT, aI);
            proc(A1, B1, aP, aT, aI);
            proc(A2, B2, aP, aT, aI);
        }
        flush(aP, aT, aI, pkP, pkT, pkI);  // 36 increments <= 63 capacity
        k += 9;
    }
    {   // Tail: leftover full iterations (<=8) + ragged remainder (<=1 int4).
        unsigned long long aP = 0ull, aT = 0ull, aI = 0ull;
        for (; k < nfull; k++) {
            const int4 a = p[i];
            const int4 b = t[i];
            i += stride;
            proc(a, b, aP, aT, aI);
        }
        if (i < n4_per_batch) proc(p[i], t[i], aP, aT, aI);
        flush(aP, aT, aI, pkP, pkT, pkI);  // <= 36 increments
    }

    // Unpack, warp butterfly reduce, one smem atomic per warp per counter.
    unsigned P[NC], T[NC], I[NC];
#pragma unroll
    for (int c = 0; c < NC; c++) {
        const int r = c >> 1;
        const int shl = (c & 1) * 16;
        P[c] = (pkP[r] >> shl) & 0xFFFFu;
        T[c] = (pkT[r] >> shl) & 0xFFFFu;
        I[c] = (pkI[r] >> shl) & 0xFFFFu;
    }
#pragma unroll
    for (int c = 0; c < NC; c++) {
#pragma unroll
        for (int off = 16; off; off >>= 1) {
            P[c] += __shfl_xor_sync(0xFFFFFFFFu, P[c], off);
            T[c] += __shfl_xor_sync(0xFFFFFFFFu, T[c], off);
            I[c] += __shfl_xor_sync(0xFFFFFFFFu, I[c], off);
        }
    }
    if ((threadIdx.x & 31) == 0) {
#pragma unroll
        for (int c = 0; c < NC; c++) {
            atomicAdd(&sh[c], P[c]);
            atomicAdd(&sh[NC + c], T[c]);
            atomicAdd(&sh[2 * NC + c], I[c]);
        }
    }
    __syncthreads();
    if (threadIdx.x < 3 * NC)
        atomicAdd(&(&g_hist[n][0][0])[threadIdx.x], sh[threadIdx.x]);

    // Last-block-done finalize + self-rezero (graph-replay safe).
    __threadfence();
    if (threadIdx.x == 0) {
        unsigned ticket = atomicAdd(&g_done, 1u);
        s_last = (ticket == (unsigned)(nblocks_total - 1)) ? 1u : 0u;
    }
    __syncthreads();
    if (s_last) {
        if (threadIdx.x == 0) {
            __threadfence();
            float acc = 0.0f;
#pragma unroll
            for (int b = 0; b < NB; b++) {
                float sumT = 0.0f;
#pragma unroll
                for (int c = 0; c < NC; c++) sumT += (float)g_hist[b][1][c];
                const float winv = (sumT > 0.0f) ? 1.0f / (sumT * (float)NB) : 0.0f;
#pragma unroll
                for (int c = 0; c < NC; c++) {
                    const float Pp = (float)g_hist[b][0][c];
                    const float Tt = (float)g_hist[b][1][c];
                    const float Ii = (float)g_hist[b][2][c];
                    const float d = Pp + Tt;
                    if (d > 0.0f) acc += (Tt * winv) * (2.0f * Ii / d);
                }
            }
            out[0] = 1.0f - acc;
        }
        __syncthreads();  // finalize read complete before re-zeroing
        if (threadIdx.x < NB * 3 * NC) (&g_hist[0][0][0])[threadIdx.x] = 0u;
        if (threadIdx.x == 0) g_done = 0u;
    }
}

extern "C" void kernel_launch(void* const* d_in, const int* in_sizes, int n_in,
                              void* d_out, int out_size) {
    const int4* yp = (const int4*)d_in[0];
    const int4* yt = (const int4*)d_in[1];
    const int total = in_sizes[0];     // 16,384,000
    const int per_batch = total / NB;  // 4,096,000
    const int n4 = per_batch / 4;      // 1,024,000 int4 per batch

    dim3 grid(74, NB);  // 296 CTAs x 512 threads = 2 CTAs/SM
    dice_fused_kernel<<<grid, 512>>>(yp, yt, n4, 74 * NB, (float*)d_out);
}

// round 6
// speedup vs baseline: 1.2366x; 1.2366x over previous
#include <cuda_runtime.h>

// DiceFromLabelsLoss — single fused kernel, round 6.
// Per (batch, class c in 1..9): P=#(yp==c), T=#(yt==c), I=#(yp==c && yt==c).
// loss = 1 - sum_n sum_c [P+T>0] * (T / sumT / NB) * (2I/(P+T))
//
// Compile-time grid stride -> all hot-loop loads are [Rptr+imm] with one
// pointer bump per 4 iterations; 4 int4-pairs staged per group (8 LDG.128
// in flight); 64-bit packed histogram accumulators (10 classes x 6-bit
// fields), flushed every 12 iterations into per-thread smem ushort totals
// (own column, no conflicts, no syncs) to keep register pressure low.

#define NB 4
#define NC 9
#define BX 74
#define TPB 512
#define STRIDE (BX * TPB)  // 37888 int4 per grid-stride step

__device__ unsigned g_hist[NB][3][NC];  // [batch][{P,T,I}][class-1]
__device__ unsigned g_done;

__device__ __forceinline__ void proc(const int4 a, const int4 b,
                                     unsigned long long& aP,
                                     unsigned long long& aT,
                                     unsigned long long& aI) {
    const int va[4] = {a.x, a.y, a.z, a.w};
    const int vb[4] = {b.x, b.y, b.z, b.w};
#pragma unroll
    for (int j = 0; j < 4; j++) {
        const unsigned long long pa = 1ull << (6 * va[j]);
        aP += pa;
        aT += 1ull << (6 * vb[j]);
        if (va[j] == vb[j]) aI += pa;
    }
}

__global__ __launch_bounds__(TPB, 2) void dice_fused_kernel(
    const int4* __restrict__ yp, const int4* __restrict__ yt,
    int n4_per_batch, int nblocks_total, float* __restrict__ out) {
    const int n = blockIdx.y;
    const int tid = threadIdx.x;
    const int base = blockIdx.x * TPB + tid;

    // Per-thread running totals in smem (own column -> conflict-free, no syncs).
    // Max per-thread per-class count ~= 4 * 28 = 112 << 65535.
    __shared__ unsigned short tot[3][NC][TPB];
    __shared__ unsigned sh[3 * NC];
    __shared__ unsigned s_last;
#pragma unroll
    for (int x = 0; x < 3; x++)
#pragma unroll
        for (int c = 0; c < NC; c++) tot[x][c][tid] = 0;
    if (tid < 3 * NC) sh[tid] = 0u;
    __syncthreads();

    const int4* __restrict__ pp = yp + (size_t)n * n4_per_batch + base;
    const int4* __restrict__ pt = yt + (size_t)n * n4_per_batch + base;
    const int nfull = n4_per_batch / STRIDE;

#define FLUSH(aP, aT, aI)                                             \
    {                                                                 \
        _Pragma("unroll") for (int c = 1; c <= NC; c++) {             \
            tot[0][c - 1][tid] += (unsigned short)((aP >> (6 * c)) & 63u); \
            tot[1][c - 1][tid] += (unsigned short)((aT >> (6 * c)) & 63u); \
            tot[2][c - 1][tid] += (unsigned short)((aI >> (6 * c)) & 63u); \
        }                                                             \
    }

    int k = 0;
    while (k + 12 <= nfull) {
        unsigned long long aP = 0ull, aT = 0ull, aI = 0ull;
#pragma unroll
        for (int g = 0; g < 3; g++) {
            // 8 LDG.128 with immediate offsets, then one pointer bump.
            const int4 A0 = pp[0];
            const int4 B0 = pt[0];
            const int4 A1 = pp[STRIDE];
            const int4 B1 = pt[STRIDE];
            const int4 A2 = pp[2 * STRIDE];
            const int4 B2 = pt[2 * STRIDE];
            const int4 A3 = pp[3 * STRIDE];
            const int4 B3 = pt[3 * STRIDE];
            pp += 4 * STRIDE;
            pt += 4 * STRIDE;
            proc(A0, B0, aP, aT, aI);
            proc(A1, B1, aP, aT, aI);
            proc(A2, B2, aP, aT, aI);
            proc(A3, B3, aP, aT, aI);
        }
        FLUSH(aP, aT, aI)  // 48 increments <= 63 field capacity
        k += 12;
    }
    {   // Tail: leftover guard-free iterations (<=11) + ragged remainder.
        unsigned long long aP = 0ull, aT = 0ull, aI = 0ull;
        for (; k < nfull; k++) {
            const int4 a = pp[0];
            const int4 b = pt[0];
            pp += STRIDE;
            pt += STRIDE;
            proc(a, b, aP, aT, aI);
        }
        if (base + nfull * STRIDE < n4_per_batch) proc(pp[0], pt[0], aP, aT, aI);
        FLUSH(aP, aT, aI)  // <= 48 increments
    }
#undef FLUSH

    // Read back own totals, warp butterfly reduce, one smem atomic per warp.
    unsigned P[NC], T[NC], I[NC];
#pragma unroll
    for (int c = 0; c < NC; c++) {
        P[c] = tot[0][c][tid];
        T[c] = tot[1][c][tid];
        I[c] = tot[2][c][tid];
    }
#pragma unroll
    for (int c = 0; c < NC; c++) {
#pragma unroll
        for (int off = 16; off; off >>= 1) {
            P[c] += __shfl_xor_sync(0xFFFFFFFFu, P[c], off);
            T[c] += __shfl_xor_sync(0xFFFFFFFFu, T[c], off);
            I[c] += __shfl_xor_sync(0xFFFFFFFFu, I[c], off);
        }
    }
    if ((tid & 31) == 0) {
#pragma unroll
        for (int c = 0; c < NC; c++) {
            atomicAdd(&sh[c], P[c]);
            atomicAdd(&sh[NC + c], T[c]);
            atomicAdd(&sh[2 * NC + c], I[c]);
        }
    }
    __syncthreads();
    if (tid < 3 * NC)
        atomicAdd(&(&g_hist[n][0][0])[tid], sh[tid]);

    // Last-block-done finalize + self-rezero (graph-replay safe).
    __threadfence();
    if (tid == 0) {
        unsigned ticket = atomicAdd(&g_done, 1u);
        s_last = (ticket == (unsigned)(nblocks_total - 1)) ? 1u : 0u;
    }
    __syncthreads();
    if (s_last) {
        if (tid == 0) {
            __threadfence();
            float acc = 0.0f;
#pragma unroll
            for (int b = 0; b < NB; b++) {
                float sumT = 0.0f;
#pragma unroll
                for (int c = 0; c < NC; c++) sumT += (float)g_hist[b][1][c];
                const float winv = (sumT > 0.0f) ? 1.0f / (sumT * (float)NB) : 0.0f;
#pragma unroll
                for (int c = 0; c < NC; c++) {
                    const float Pp = (float)g_hist[b][0][c];
                    const float Tt = (float)g_hist[b][1][c];
                    const float Ii = (float)g_hist[b][2][c];
                    const float d = Pp + Tt;
                    if (d > 0.0f) acc += (Tt * winv) * (2.0f * Ii / d);
                }
            }
            out[0] = 1.0f - acc;
        }
        __syncthreads();  // finalize read complete before re-zeroing
        if (tid < NB * 3 * NC) (&g_hist[0][0][0])[tid] = 0u;
        if (tid == 0) g_done = 0u;
    }
}

extern "C" void kernel_launch(void* const* d_in, const int* in_sizes, int n_in,
                              void* d_out, int out_size) {
    const int4* yp = (const int4*)d_in[0];
    const int4* yt = (const int4*)d_in[1];
    const int total = in_sizes[0];     // 16,384,000
    const int per_batch = total / NB;  // 4,096,000
    const int n4 = per_batch / 4;      // 1,024,000 int4 per batch

    dim3 grid(BX, NB);  // 296 CTAs x 512 threads = 2 CTAs/SM
    dice_fused_kernel<<<grid, TPB>>>(yp, yt, n4, BX * NB, (float*)d_out);
}